// round 10
// baseline (speedup 1.0000x reference)
#include <cuda_runtime.h>
#include <cstdint>
#include <math.h>

#define TPB 128   // 4 warps: one part each (R8 split)
#define EPB 32    // elements per stage (= lanes per warp)
#define SPB 2     // stages per block -> 64 elements per block

// ---- in-place right-multiply by elementary rotations (R = R @ Rot) ----
__device__ __forceinline__ void mul_rx(float R[9], float s, float c) {
#pragma unroll
    for (int i = 0; i < 3; i++) {
        float a = R[3*i+1], b = R[3*i+2];
        R[3*i+1] = c*a + s*b;
        R[3*i+2] = c*b - s*a;
    }
}
__device__ __forceinline__ void mul_ry(float R[9], float s, float c) {
#pragma unroll
    for (int i = 0; i < 3; i++) {
        float a = R[3*i+0], b = R[3*i+2];
        R[3*i+0] = c*a - s*b;
        R[3*i+2] = s*a + c*b;
    }
}
__device__ __forceinline__ void mul_rz(float R[9], float s, float c) {
#pragma unroll
    for (int i = 0; i < 3; i++) {
        float a = R[3*i+0], b = R[3*i+1];
        R[3*i+0] = c*a + s*b;
        R[3*i+1] = c*b - s*a;
    }
}
// R = R @ M (M row-major 3x3)
__device__ __forceinline__ void mul_mat(float R[9], const float M[9]) {
#pragma unroll
    for (int i = 0; i < 3; i++) {
        float a = R[3*i], b = R[3*i+1], cc = R[3*i+2];
        R[3*i+0] = a*M[0] + b*M[3] + cc*M[6];
        R[3*i+1] = a*M[1] + b*M[4] + cc*M[7];
        R[3*i+2] = a*M[2] + b*M[5] + cc*M[8];
    }
}

__device__ __forceinline__ void store3(float* o, int node, const float t[3]) {
    o[3*node+0] = t[0]; o[3*node+1] = t[1]; o[3*node+2] = t[2];
}

#define SCQ(j, lo, hi, S, C) do { \
    float _q = fminf(fmaxf(q[j], (lo)), (hi)); \
    __sincosf(_q, &(S), &(C)); } while (0)

#define LOAD4(v) do { float4 _f = __ldg(ag4 + (v)); \
    q[4*(v)+0] = _f.x; q[4*(v)+1] = _f.y; q[4*(v)+2] = _f.z; q[4*(v)+3] = _f.w; } while (0)

// palm chain: nodes 0,1 -> R1, t1 (2 sincos)
__device__ __forceinline__ void palm(const float q[24], float R1[9], float t1[3]) {
    float s0, c0, s1_, c1_;
    SCQ(0, -0.523599f, 0.174533f, s0, c0);
    SCQ(1, -0.698132f, 0.488692f, s1_, c1_);
    t1[0] = 0.034f * s0; t1[1] = 0.f; t1[2] = 0.034f * c0;
    R1[0] = c0;   R1[1] = s1_*s0;  R1[2] = c1_*s0;
    R1[3] = 0.f;  R1[4] = c1_;     R1[5] = -s1_;
    R1[6] = -s0;  R1[7] = s1_*c0;  R1[8] = c1_*c0;
}

// Standard 4-joint finger: knuckle Ry(sA,cA) at (tx,0,tz), then Rx,Rx,Rx, fixed tip.
__device__ __forceinline__ void finger(const float R1[9], const float t1[3], float* o, int node0,
                                       float sA, float cA, float tx, float tz,
                                       float s1, float c1, float s2, float c2, float s3, float c3) {
    float R[9], t[3];
#pragma unroll
    for (int i = 0; i < 9; i++) R[i] = R1[i];
    t[0] = t1[0] + tx*R1[0] + tz*R1[2];
    t[1] = t1[1] + tx*R1[3] + tz*R1[5];
    t[2] = t1[2] + tx*R1[6] + tz*R1[8];
    store3(o, node0, t);          // knuckle
    mul_ry(R, sA, cA);
    store3(o, node0+1, t);        // proximal base (zero trans)
    mul_rx(R, s1, c1);
    t[0] += 0.045f*R[2]; t[1] += 0.045f*R[5]; t[2] += 0.045f*R[8];
    store3(o, node0+2, t);
    mul_rx(R, s2, c2);
    t[0] += 0.025f*R[2]; t[1] += 0.025f*R[5]; t[2] += 0.025f*R[8];
    store3(o, node0+3, t);
    mul_rx(R, s3, c3);
    t[0] += 0.026f*R[2]; t[1] += 0.026f*R[5]; t[2] += 0.026f*R[8];
    store3(o, node0+4, t);        // tip
}

// Compute this part's nodes for element e into o[0..86]. (R8 4-way partition)
__device__ __forceinline__ void compute_elem(const float* __restrict__ angles,
                                             int e, int part, float* o) {
    const float4* ag4 = (const float4*)(angles + (size_t)e * 24);
    float q[24];
    LOAD4(0);                                   // q[0..3] (everyone needs palm q0,q1)
    float R1[9], t1[3];

    if (part == 0) {
        // ---- fingers 1 & 2: nodes 2-11, joints 2-9 ----
        LOAD4(1); LOAD4(2);
        palm(q, R1, t1);
        {
            float sA,cA,s1,c1,s2,c2,s3,c3;
            SCQ(2, -0.349066f, 0.349066f, sA, cA);
            SCQ(3, 0.f, 1.5708f, s1, c1);
            SCQ(4, 0.f, 1.5708f, s2, c2);
            SCQ(5, 0.f, 1.5708f, s3, c3);
            finger(R1, t1, o, 2, sA, cA, -0.033f, 0.095f, s1,c1, s2,c2, s3,c3);
        }
        {
            float sA,cA,s1,c1,s2,c2,s3,c3;
            SCQ(6, -0.349066f, 0.349066f, sA, cA);
            SCQ(7, 0.f, 1.5708f, s1, c1);
            SCQ(8, 0.f, 1.5708f, s2, c2);
            SCQ(9, 0.f, 1.5708f, s3, c3);
            finger(R1, t1, o, 7, sA, cA, -0.011f, 0.099f, s1,c1, s2,c2, s3,c3);
        }
    } else if (part == 1) {
        // ---- nodes 0,1 + ring finger: nodes 12-16, joints 10-13 ----
        LOAD4(2); LOAD4(3);
        palm(q, R1, t1);
        o[0] = 0.f; o[1] = 0.f; o[2] = 0.f;
        o[3] = t1[0]; o[4] = t1[1]; o[5] = t1[2];
        float sA,cA,s1,c1,s2,c2,s3,c3;
        SCQ(10, -0.349066f, 0.349066f, sA, cA);
        SCQ(11, 0.f, 1.5708f, s1, c1);
        SCQ(12, 0.f, 1.5708f, s2, c2);
        SCQ(13, 0.f, 1.5708f, s3, c3);
        finger(R1, t1, o, 12, -sA, cA, 0.011f, 0.095f, s1,c1, s2,c2, s3,c3);
    } else if (part == 2) {
        // ---- Little finger: nodes 17-22, joints 14-18 ----
        LOAD4(3); LOAD4(4);
        palm(q, R1, t1);
        float s14,c14,s15,c15,s16,c16,s17,c17,s18,c18;
        SCQ(14, 0.f, 0.785398f, s14, c14);
        SCQ(15, -0.349066f, 0.349066f, s15, c15);
        SCQ(16, 0.f, 1.5708f, s16, c16);
        SCQ(17, 0.f, 1.5708f, s17, c17);
        SCQ(18, 0.f, 1.5708f, s18, c18);
        const float ax = 0.573576f, az = -0.819152f;
        float omc = 1.f - c14;
        float M[9] = {
            c14 + omc*ax*ax, -s14*az,  omc*ax*az,
            s14*az,           c14,    -s14*ax,
            omc*ax*az,        s14*ax,  c14 + omc*az*az
        };
        float R[9], t[3];
#pragma unroll
        for (int i = 0; i < 9; i++) R[i] = R1[i];
        t[0] = t1[0] + 0.033f*R1[0] + 0.02071f*R1[2];
        t[1] = t1[1] + 0.033f*R1[3] + 0.02071f*R1[5];
        t[2] = t1[2] + 0.033f*R1[6] + 0.02071f*R1[8];
        store3(o, 17, t);
        mul_mat(R, M);                            // R17
        t[0] += 0.06579f*R[2]; t[1] += 0.06579f*R[5]; t[2] += 0.06579f*R[8];
        store3(o, 18, t);
        mul_ry(R, -s15, c15);                     // joint 15 axis (0,-1,0)
        store3(o, 19, t);
        mul_rx(R, s16, c16);
        t[0] += 0.045f*R[2]; t[1] += 0.045f*R[5]; t[2] += 0.045f*R[8];
        store3(o, 20, t);
        mul_rx(R, s17, c17);
        t[0] += 0.025f*R[2]; t[1] += 0.025f*R[5]; t[2] += 0.025f*R[8];
        store3(o, 21, t);
        mul_rx(R, s18, c18);
        t[0] += 0.026f*R[2]; t[1] += 0.026f*R[5]; t[2] += 0.026f*R[8];
        store3(o, 22, t);
    } else {
        // ---- Thumb: nodes 23-28, joints 19-23 ----
        LOAD4(4); LOAD4(5);
        palm(q, R1, t1);
        float s19,c19,s20,c20,s21,c21,s22,c22,s23,c23;
        SCQ(19, -1.0472f, 1.0472f, s19, c19);
        SCQ(20, 0.f, 1.22173f, s20, c20);
        SCQ(21, -0.20944f, 0.20944f, s21, c21);
        SCQ(22, -0.698132f, 0.698132f, s22, c22);
        SCQ(23, 0.f, 1.5708f, s23, c23);
        const float bx = 0.382683f, bz = -0.92388f;
        const float QB[9] = {
            1.f - 2.f*bz*bz, 0.f,              2.f*bx*bz,
            0.f,             1.f - 2.f*(bx*bx + bz*bz), 0.f,
            2.f*bx*bz,       0.f,              1.f - 2.f*bx*bx
        };
        const float dw = 0.707107f, dz = -0.707107f;
        const float QD[9] = {
            1.f - 2.f*dz*dz, -2.f*dz*dw, 0.f,
            2.f*dz*dw,        1.f - 2.f*dz*dz, 0.f,
            0.f,              0.f,       1.f
        };
        float R[9], t[3];
#pragma unroll
        for (int i = 0; i < 9; i++) R[i] = R1[i];
        t[0] = t1[0] - 0.034f*R1[0] - 0.0085f*R1[1] + 0.029f*R1[2];
        t[1] = t1[1] - 0.034f*R1[3] - 0.0085f*R1[4] + 0.029f*R1[5];
        t[2] = t1[2] - 0.034f*R1[6] - 0.0085f*R1[7] + 0.029f*R1[8];
        store3(o, 23, t);
        mul_mat(R, QB);
        mul_rz(R, s19, c19);                      // R23
        store3(o, 24, t);                         // zero trans
        mul_rx(R, -s20, c20);                     // joint 20 axis (-1,0,0)
        t[0] += 0.038f*R[2]; t[1] += 0.038f*R[5]; t[2] += 0.038f*R[8];
        store3(o, 25, t);
        mul_rx(R, s21, c21);
        store3(o, 26, t);                         // zero trans
        mul_ry(R, -s22, c22);                     // joint 22 axis (0,-1,0)
        t[0] += 0.032f*R[2]; t[1] += 0.032f*R[5]; t[2] += 0.032f*R[8];
        store3(o, 27, t);
        mul_mat(R, QD);
        mul_rx(R, s23, c23);                      // R27
        t[0] += 0.0275f*R[2]; t[1] += 0.0275f*R[5]; t[2] += 0.0275f*R[8];
        store3(o, 28, t);
    }
}

__global__ void __launch_bounds__(TPB, 8)
shadowhand_fk_kernel(const float* __restrict__ angles, float* __restrict__ out, int B) {
    __shared__ __align__(16) float sm[SPB][EPB * 87];  // 2 x 11136 B

    const int lane = threadIdx.x & 31;
    const int part = threadIdx.x >> 5;     // 0..3, warp-uniform (R8 split)

#pragma unroll
    for (int s = 0; s < SPB; s++) {
        const int eb = blockIdx.x * (SPB * EPB) + s * EPB;
        int nv = B - eb;
        if (nv > EPB) nv = EPB;

        if (nv > 0 && lane < nv)
            compute_elem(angles, eb + lane, part, sm[s] + lane * 87);

        __syncthreads();

        if (nv == EPB) {
            // Issue async bulk store; do NOT wait here (overlap with next stage).
            if (threadIdx.x == 0) {
                asm volatile("fence.proxy.async.shared::cta;" ::: "memory");
                unsigned int saddr;
                asm("{ .reg .u64 t; cvta.to.shared.u64 t, %1; cvt.u32.u64 %0, t; }"
                    : "=r"(saddr) : "l"(sm[s]));
                asm volatile(
                    "cp.async.bulk.global.shared::cta.bulk_group [%0], [%1], %2;"
                    :: "l"(out + (size_t)eb * 87), "r"(saddr), "n"(EPB * 87 * 4)
                    : "memory");
                asm volatile("cp.async.bulk.commit_group;" ::: "memory");
            }
        } else if (nv > 0) {
            int tot = nv * 87;
            for (int i = threadIdx.x; i < tot; i += TPB)
                out[(size_t)eb * 87 + i] = sm[s][i];
        }
    }

    // Single drain of all committed bulk groups before smem is released.
    if (threadIdx.x == 0)
        asm volatile("cp.async.bulk.wait_group.read 0;" ::: "memory");
}

extern "C" void kernel_launch(void* const* d_in, const int* in_sizes, int n_in,
                              void* d_out, int out_size) {
    const float* angles = (const float*)d_in[0];
    float* out = (float*)d_out;
    int B = in_sizes[0] / 24;
    int per_block = SPB * EPB;
    int grid = (B + per_block - 1) / per_block;
    shadowhand_fk_kernel<<<grid, TPB>>>(angles, out, B);
}

// round 11
// speedup vs baseline: 1.0863x; 1.0863x over previous
#include <cuda_runtime.h>
#include <cstdint>
#include <math.h>

#define TPB 128   // 4 warps: one part each (R8 split)
#define EPB 32    // elements per block (= lanes per warp)
#define QSTRIDE 25  // smem input stride: gcd(25,32)=1 -> conflict-free

// ---- in-place right-multiply by elementary rotations (R = R @ Rot) ----
__device__ __forceinline__ void mul_rx(float R[9], float s, float c) {
#pragma unroll
    for (int i = 0; i < 3; i++) {
        float a = R[3*i+1], b = R[3*i+2];
        R[3*i+1] = c*a + s*b;
        R[3*i+2] = c*b - s*a;
    }
}
__device__ __forceinline__ void mul_ry(float R[9], float s, float c) {
#pragma unroll
    for (int i = 0; i < 3; i++) {
        float a = R[3*i+0], b = R[3*i+2];
        R[3*i+0] = c*a - s*b;
        R[3*i+2] = s*a + c*b;
    }
}
__device__ __forceinline__ void mul_rz(float R[9], float s, float c) {
#pragma unroll
    for (int i = 0; i < 3; i++) {
        float a = R[3*i+0], b = R[3*i+1];
        R[3*i+0] = c*a + s*b;
        R[3*i+1] = c*b - s*a;
    }
}
// R = R @ M (M row-major 3x3)
__device__ __forceinline__ void mul_mat(float R[9], const float M[9]) {
#pragma unroll
    for (int i = 0; i < 3; i++) {
        float a = R[3*i], b = R[3*i+1], cc = R[3*i+2];
        R[3*i+0] = a*M[0] + b*M[3] + cc*M[6];
        R[3*i+1] = a*M[1] + b*M[4] + cc*M[7];
        R[3*i+2] = a*M[2] + b*M[5] + cc*M[8];
    }
}

__device__ __forceinline__ void store3(float* o, int node, const float t[3]) {
    o[3*node+0] = t[0]; o[3*node+1] = t[1]; o[3*node+2] = t[2];
}

// clamp + sincos reading joint j from smem-resident qs[]
#define SCQ(j, lo, hi, S, C) do { \
    float _q = fminf(fmaxf(qs[j], (lo)), (hi)); \
    __sincosf(_q, &(S), &(C)); } while (0)

// palm chain: nodes 0,1 -> R1, t1 (2 sincos)
__device__ __forceinline__ void palm(const float* qs, float R1[9], float t1[3]) {
    float s0, c0, s1_, c1_;
    SCQ(0, -0.523599f, 0.174533f, s0, c0);
    SCQ(1, -0.698132f, 0.488692f, s1_, c1_);
    t1[0] = 0.034f * s0; t1[1] = 0.f; t1[2] = 0.034f * c0;
    R1[0] = c0;   R1[1] = s1_*s0;  R1[2] = c1_*s0;
    R1[3] = 0.f;  R1[4] = c1_;     R1[5] = -s1_;
    R1[6] = -s0;  R1[7] = s1_*c0;  R1[8] = c1_*c0;
}

// Standard 4-joint finger: knuckle Ry(sA,cA) at (tx,0,tz), then Rx,Rx,Rx, fixed tip.
__device__ __forceinline__ void finger(const float R1[9], const float t1[3], float* o, int node0,
                                       float sA, float cA, float tx, float tz,
                                       float s1, float c1, float s2, float c2, float s3, float c3) {
    float R[9], t[3];
#pragma unroll
    for (int i = 0; i < 9; i++) R[i] = R1[i];
    t[0] = t1[0] + tx*R1[0] + tz*R1[2];
    t[1] = t1[1] + tx*R1[3] + tz*R1[5];
    t[2] = t1[2] + tx*R1[6] + tz*R1[8];
    store3(o, node0, t);          // knuckle
    mul_ry(R, sA, cA);
    store3(o, node0+1, t);        // proximal base (zero trans)
    mul_rx(R, s1, c1);
    t[0] += 0.045f*R[2]; t[1] += 0.045f*R[5]; t[2] += 0.045f*R[8];
    store3(o, node0+2, t);
    mul_rx(R, s2, c2);
    t[0] += 0.025f*R[2]; t[1] += 0.025f*R[5]; t[2] += 0.025f*R[8];
    store3(o, node0+3, t);
    mul_rx(R, s3, c3);
    t[0] += 0.026f*R[2]; t[1] += 0.026f*R[5]; t[2] += 0.026f*R[8];
    store3(o, node0+4, t);        // tip
}

__global__ void __launch_bounds__(TPB, 10)
shadowhand_fk_kernel(const float* __restrict__ angles, float* __restrict__ out, int B) {
    __shared__ __align__(16) float sm[EPB * 87];       // 11136 B, contiguous == global span
    __shared__ float qin[EPB * QSTRIDE];               // 3200 B staged input

    const int lane = threadIdx.x & 31;
    const int part = threadIdx.x >> 5;     // 0..3, warp-uniform

    int nv = B - blockIdx.x * EPB;
    if (nv > EPB) nv = EPB;

    // ---- Stage input: coalesced float4 global loads -> stride-25 smem ----
    {
        const float4* in4 = (const float4*)(angles + (size_t)blockIdx.x * EPB * 24);
        int total4 = nv * 6;                           // 6 float4 per element
        for (int i = threadIdx.x; i < total4; i += TPB) {
            float4 f = __ldg(in4 + i);
            int e = i / 6, s = i - e * 6;
            float* d = qin + e * QSTRIDE + s * 4;
            d[0] = f.x; d[1] = f.y; d[2] = f.z; d[3] = f.w;
        }
    }
    __syncthreads();

    if (lane < nv) {
        const float* qs = qin + lane * QSTRIDE;
        float* o = sm + lane * 87;         // stride 87: gcd(87,32)=1, conflict-free
        float R1[9], t1[3];
        palm(qs, R1, t1);

        if (part == 0) {
            // ---- fingers 1 & 2: nodes 2-11, joints 2-9 ----
            {
                float sA,cA,s1,c1,s2,c2,s3,c3;
                SCQ(2, -0.349066f, 0.349066f, sA, cA);
                SCQ(3, 0.f, 1.5708f, s1, c1);
                SCQ(4, 0.f, 1.5708f, s2, c2);
                SCQ(5, 0.f, 1.5708f, s3, c3);
                finger(R1, t1, o, 2, sA, cA, -0.033f, 0.095f, s1,c1, s2,c2, s3,c3);
            }
            {
                float sA,cA,s1,c1,s2,c2,s3,c3;
                SCQ(6, -0.349066f, 0.349066f, sA, cA);
                SCQ(7, 0.f, 1.5708f, s1, c1);
                SCQ(8, 0.f, 1.5708f, s2, c2);
                SCQ(9, 0.f, 1.5708f, s3, c3);
                finger(R1, t1, o, 7, sA, cA, -0.011f, 0.099f, s1,c1, s2,c2, s3,c3);
            }
        } else if (part == 1) {
            // ---- nodes 0,1 + ring finger: nodes 12-16, joints 10-13 ----
            o[0] = 0.f; o[1] = 0.f; o[2] = 0.f;
            o[3] = t1[0]; o[4] = t1[1]; o[5] = t1[2];
            float sA,cA,s1,c1,s2,c2,s3,c3;
            SCQ(10, -0.349066f, 0.349066f, sA, cA);
            SCQ(11, 0.f, 1.5708f, s1, c1);
            SCQ(12, 0.f, 1.5708f, s2, c2);
            SCQ(13, 0.f, 1.5708f, s3, c3);
            finger(R1, t1, o, 12, -sA, cA, 0.011f, 0.095f, s1,c1, s2,c2, s3,c3);
        } else if (part == 2) {
            // ---- Little finger: nodes 17-22, joints 14-18 ----
            float s14,c14,s15,c15,s16,c16,s17,c17,s18,c18;
            SCQ(14, 0.f, 0.785398f, s14, c14);
            SCQ(15, -0.349066f, 0.349066f, s15, c15);
            SCQ(16, 0.f, 1.5708f, s16, c16);
            SCQ(17, 0.f, 1.5708f, s17, c17);
            SCQ(18, 0.f, 1.5708f, s18, c18);
            const float ax = 0.573576f, az = -0.819152f;
            float omc = 1.f - c14;
            float M[9] = {
                c14 + omc*ax*ax, -s14*az,  omc*ax*az,
                s14*az,           c14,    -s14*ax,
                omc*ax*az,        s14*ax,  c14 + omc*az*az
            };
            float R[9], t[3];
#pragma unroll
            for (int i = 0; i < 9; i++) R[i] = R1[i];
            t[0] = t1[0] + 0.033f*R1[0] + 0.02071f*R1[2];
            t[1] = t1[1] + 0.033f*R1[3] + 0.02071f*R1[5];
            t[2] = t1[2] + 0.033f*R1[6] + 0.02071f*R1[8];
            store3(o, 17, t);
            mul_mat(R, M);                            // R17
            t[0] += 0.06579f*R[2]; t[1] += 0.06579f*R[5]; t[2] += 0.06579f*R[8];
            store3(o, 18, t);
            mul_ry(R, -s15, c15);                     // joint 15 axis (0,-1,0)
            store3(o, 19, t);
            mul_rx(R, s16, c16);
            t[0] += 0.045f*R[2]; t[1] += 0.045f*R[5]; t[2] += 0.045f*R[8];
            store3(o, 20, t);
            mul_rx(R, s17, c17);
            t[0] += 0.025f*R[2]; t[1] += 0.025f*R[5]; t[2] += 0.025f*R[8];
            store3(o, 21, t);
            mul_rx(R, s18, c18);
            t[0] += 0.026f*R[2]; t[1] += 0.026f*R[5]; t[2] += 0.026f*R[8];
            store3(o, 22, t);
        } else {
            // ---- Thumb: nodes 23-28, joints 19-23 ----
            float s19,c19,s20,c20,s21,c21,s22,c22,s23,c23;
            SCQ(19, -1.0472f, 1.0472f, s19, c19);
            SCQ(20, 0.f, 1.22173f, s20, c20);
            SCQ(21, -0.20944f, 0.20944f, s21, c21);
            SCQ(22, -0.698132f, 0.698132f, s22, c22);
            SCQ(23, 0.f, 1.5708f, s23, c23);
            const float bx = 0.382683f, bz = -0.92388f;
            const float QB[9] = {
                1.f - 2.f*bz*bz, 0.f,              2.f*bx*bz,
                0.f,             1.f - 2.f*(bx*bx + bz*bz), 0.f,
                2.f*bx*bz,       0.f,              1.f - 2.f*bx*bx
            };
            const float dw = 0.707107f, dz = -0.707107f;
            const float QD[9] = {
                1.f - 2.f*dz*dz, -2.f*dz*dw, 0.f,
                2.f*dz*dw,        1.f - 2.f*dz*dz, 0.f,
                0.f,              0.f,       1.f
            };
            float R[9], t[3];
#pragma unroll
            for (int i = 0; i < 9; i++) R[i] = R1[i];
            t[0] = t1[0] - 0.034f*R1[0] - 0.0085f*R1[1] + 0.029f*R1[2];
            t[1] = t1[1] - 0.034f*R1[3] - 0.0085f*R1[4] + 0.029f*R1[5];
            t[2] = t1[2] - 0.034f*R1[6] - 0.0085f*R1[7] + 0.029f*R1[8];
            store3(o, 23, t);
            mul_mat(R, QB);
            mul_rz(R, s19, c19);                      // R23
            store3(o, 24, t);                         // zero trans
            mul_rx(R, -s20, c20);                     // joint 20 axis (-1,0,0)
            t[0] += 0.038f*R[2]; t[1] += 0.038f*R[5]; t[2] += 0.038f*R[8];
            store3(o, 25, t);
            mul_rx(R, s21, c21);
            store3(o, 26, t);                         // zero trans
            mul_ry(R, -s22, c22);                     // joint 22 axis (0,-1,0)
            t[0] += 0.032f*R[2]; t[1] += 0.032f*R[5]; t[2] += 0.032f*R[8];
            store3(o, 27, t);
            mul_mat(R, QD);
            mul_rx(R, s23, c23);                      // R27
            t[0] += 0.0275f*R[2]; t[1] += 0.0275f*R[5]; t[2] += 0.0275f*R[8];
            store3(o, 28, t);
        }
    }

    __syncthreads();

    size_t base = (size_t)blockIdx.x * (EPB * 87);
    if (nv == EPB) {
        // Single bulk copy: smem (contiguous, 11136B, 16B-aligned) -> global.
        if (threadIdx.x == 0) {
            asm volatile("fence.proxy.async.shared::cta;" ::: "memory");
            unsigned int saddr;
            asm("{ .reg .u64 t; cvta.to.shared.u64 t, %1; cvt.u32.u64 %0, t; }"
                : "=r"(saddr) : "l"(sm));
            asm volatile(
                "cp.async.bulk.global.shared::cta.bulk_group [%0], [%1], %2;"
                :: "l"(out + base), "r"(saddr), "n"(EPB * 87 * 4)
                : "memory");
            asm volatile("cp.async.bulk.commit_group;" ::: "memory");
            asm volatile("cp.async.bulk.wait_group.read 0;" ::: "memory");
        }
    } else if (nv > 0) {
        int tot = nv * 87;
        for (int i = threadIdx.x; i < tot; i += TPB)
            out[base + i] = sm[i];
    }
}

extern "C" void kernel_launch(void* const* d_in, const int* in_sizes, int n_in,
                              void* d_out, int out_size) {
    const float* angles = (const float*)d_in[0];
    float* out = (float*)d_out;
    int B = in_sizes[0] / 24;
    int grid = (B + EPB - 1) / EPB;
    shadowhand_fk_kernel<<<grid, TPB>>>(angles, out, B);
}